// round 2
// baseline (speedup 1.0000x reference)
#include <cuda_runtime.h>
#include <cstdint>

// Problem constants (match reference_code)
#define NN 50000
#define EE 800000
#define DD 64
#define KHOPS 3

// ----------------------------------------------------------------------------
// Scratch (device globals; no allocation allowed)
// ----------------------------------------------------------------------------
__device__ float g_h[NN * DD];      // ping
__device__ float g_t[NN * DD];      // pong
__device__ int   g_deg[NN];         // in-degree histogram
__device__ int   g_rowptr[NN + 1];  // CSR row pointers (by dst)
__device__ int   g_cursor[NN];      // scatter cursors
__device__ int   g_csr_src[EE];     // gathered src per CSR slot
__device__ float g_csr_w[EE];       // gathered w per CSR slot

// ----------------------------------------------------------------------------
// 1) init: g_h = x ; out = 0.25*x ; zero degree histogram
// ----------------------------------------------------------------------------
__global__ void init_kernel(const float* __restrict__ x, float* __restrict__ out) {
    int i = blockIdx.x * blockDim.x + threadIdx.x;
    int stride = gridDim.x * blockDim.x;
    for (int idx = i; idx < NN * DD; idx += stride) {
        float v = x[idx];
        g_h[idx] = v;
        out[idx] = 0.25f * v;
    }
    for (int idx = i; idx < NN; idx += stride) {
        g_deg[idx] = 0;
    }
}

// ----------------------------------------------------------------------------
// 2) count in-degree per dst
// ----------------------------------------------------------------------------
__global__ void count_kernel(const int* __restrict__ dst) {
    int e = blockIdx.x * blockDim.x + threadIdx.x;
    if (e < EE) atomicAdd(&g_deg[dst[e]], 1);
}

// ----------------------------------------------------------------------------
// 3) exclusive scan over g_deg -> g_rowptr, g_cursor  (single block)
// ----------------------------------------------------------------------------
__global__ void scan_kernel() {
    __shared__ int smem[1024];
    __shared__ int carry_s;
    int tid = threadIdx.x;
    if (tid == 0) carry_s = 0;
    __syncthreads();

    for (int base = 0; base < NN; base += 1024) {
        int i = base + tid;
        int v = (i < NN) ? g_deg[i] : 0;
        smem[tid] = v;
        __syncthreads();
        // Hillis-Steele inclusive scan
        #pragma unroll
        for (int off = 1; off < 1024; off <<= 1) {
            int t = 0;
            if (tid >= off) t = smem[tid - off];
            __syncthreads();
            smem[tid] += t;
            __syncthreads();
        }
        int incl = smem[tid] + carry_s;
        if (i < NN) {
            g_rowptr[i + 1] = incl;
            g_cursor[i] = incl - v;   // exclusive
        }
        __syncthreads();
        if (tid == 1023) carry_s = incl;
        __syncthreads();
    }
    if (tid == 0) g_rowptr[0] = 0;
}

// ----------------------------------------------------------------------------
// 4) scatter edges into CSR-by-dst slots
// ----------------------------------------------------------------------------
__global__ void fill_kernel(const int* __restrict__ src,
                            const int* __restrict__ dst,
                            const float* __restrict__ w) {
    int e = blockIdx.x * blockDim.x + threadIdx.x;
    if (e >= EE) return;
    int d = dst[e];
    int pos = atomicAdd(&g_cursor[d], 1);
    g_csr_src[pos] = src[e];
    g_csr_w[pos]   = w[e];
}

// ----------------------------------------------------------------------------
// 5) SpMM hop: one warp per dst row. Lanes hold float2 (64 floats / 32 lanes).
//    hout[row] = sum_e w_e * h[src_e] ;  out[row] += 0.25 * hout[row]
//    Zero atomics; gathers hit L2 (12.8 MB h buffer is L2-resident).
// ----------------------------------------------------------------------------
__global__ void spmm_kernel(const float* __restrict__ h,
                            float* __restrict__ hout,
                            float* __restrict__ out) {
    int warps_per_block = blockDim.x >> 5;
    int row = blockIdx.x * warps_per_block + (threadIdx.x >> 5);
    if (row >= NN) return;
    int lane = threadIdx.x & 31;

    int beg = g_rowptr[row];
    int end = g_rowptr[row + 1];

    const float2* __restrict__ h2 = (const float2*)h;

    float2 acc0 = make_float2(0.f, 0.f);
    float2 acc1 = make_float2(0.f, 0.f);

    int j = beg;
    // 2-way unroll with independent accumulators for memory-level parallelism
    for (; j + 1 < end; j += 2) {
        int   s0 = __ldg(&g_csr_src[j]);
        int   s1 = __ldg(&g_csr_src[j + 1]);
        float w0 = __ldg(&g_csr_w[j]);
        float w1 = __ldg(&g_csr_w[j + 1]);
        float2 x0 = h2[s0 * 32 + lane];
        float2 x1 = h2[s1 * 32 + lane];
        acc0.x += w0 * x0.x; acc0.y += w0 * x0.y;
        acc1.x += w1 * x1.x; acc1.y += w1 * x1.y;
    }
    if (j < end) {
        int   s0 = __ldg(&g_csr_src[j]);
        float w0 = __ldg(&g_csr_w[j]);
        float2 x0 = h2[s0 * 32 + lane];
        acc0.x += w0 * x0.x; acc0.y += w0 * x0.y;
    }

    float2 acc = make_float2(acc0.x + acc1.x, acc0.y + acc1.y);

    int idx = row * 32 + lane;
    ((float2*)hout)[idx] = acc;

    float2* o2 = (float2*)out + idx;
    float2 ov = *o2;
    ov.x += 0.25f * acc.x;
    ov.y += 0.25f * acc.y;
    *o2 = ov;
}

// ----------------------------------------------------------------------------
// launch
// ----------------------------------------------------------------------------
extern "C" void kernel_launch(void* const* d_in, const int* in_sizes, int n_in,
                              void* d_out, int out_size) {
    const float* x   = (const float*)d_in[0];
    const float* w   = (const float*)d_in[1];
    const int*   src = (const int*)d_in[2];
    const int*   dst = (const int*)d_in[3];
    float*       out = (float*)d_out;

    (void)in_sizes; (void)n_in; (void)out_size;

    float* hA; float* hB;
    cudaGetSymbolAddress((void**)&hA, g_h);
    cudaGetSymbolAddress((void**)&hB, g_t);

    // 1) init (also zeroes degree histogram)
    init_kernel<<<1024, 256>>>(x, out);
    // 2) histogram
    count_kernel<<<(EE + 255) / 256, 256>>>(dst);
    // 3) scan
    scan_kernel<<<1, 1024>>>();
    // 4) CSR scatter
    fill_kernel<<<(EE + 255) / 256, 256>>>(src, dst, w);

    // 5) K=3 hops, ping-pong h buffers, fused residual (+0.25*h) into out
    const int WPB = 8;                    // 8 warps (rows) per block
    dim3 blk(WPB * 32);
    dim3 grd((NN + WPB - 1) / WPB);
    spmm_kernel<<<grd, blk>>>(hA, hB, out);   // hop 1: x    -> g_t
    spmm_kernel<<<grd, blk>>>(hB, hA, out);   // hop 2: g_t  -> g_h
    spmm_kernel<<<grd, blk>>>(hA, hB, out);   // hop 3: g_h  -> g_t
}

// round 3
// speedup vs baseline: 1.5355x; 1.5355x over previous
#include <cuda_runtime.h>
#include <cstdint>

// Problem constants (match reference_code)
#define NN 50000
#define EE 800000
#define DD 64

#define TILE 1024
#define NBLK ((NN + TILE - 1) / TILE)   // 49

// ----------------------------------------------------------------------------
// Scratch (device globals; no allocation allowed)
// ----------------------------------------------------------------------------
__device__ float g_h[NN * DD];      // ping
__device__ float g_t[NN * DD];      // pong
__device__ int   g_deg[NN];         // in-degree histogram
__device__ int   g_rowptr[NN + 1];  // CSR row pointers (by dst)
__device__ int   g_cursor[NN];      // scatter cursors
__device__ int   g_lscan[NN];       // per-block inclusive scan
__device__ int   g_bsum[NBLK];      // block sums
__device__ int   g_boff[NBLK];      // exclusive block offsets
__device__ int2  g_csr[EE];         // packed {src, w_bits} per CSR slot

// ----------------------------------------------------------------------------
// 1) init: g_h = x ; out = 0.25*x ; zero degree histogram  (float4 vectorized)
// ----------------------------------------------------------------------------
__global__ void init_kernel(const float4* __restrict__ x4, float4* __restrict__ out4) {
    int i = blockIdx.x * blockDim.x + threadIdx.x;
    int stride = gridDim.x * blockDim.x;
    float4* h4 = (float4*)g_h;
    const int n4 = NN * DD / 4;
    for (int idx = i; idx < n4; idx += stride) {
        float4 v = x4[idx];
        h4[idx] = v;
        float4 o = make_float4(0.25f * v.x, 0.25f * v.y, 0.25f * v.z, 0.25f * v.w);
        out4[idx] = o;
    }
    for (int idx = i; idx < NN; idx += stride) g_deg[idx] = 0;
}

// ----------------------------------------------------------------------------
// 2) count in-degree per dst (no-return atomic -> REDG)
// ----------------------------------------------------------------------------
__global__ void count_kernel(const int* __restrict__ dst) {
    int e = blockIdx.x * blockDim.x + threadIdx.x;
    if (e < EE) atomicAdd(&g_deg[dst[e]], 1);
}

// ----------------------------------------------------------------------------
// 3a) per-block inclusive scan of g_deg (49 blocks, one wave)
// ----------------------------------------------------------------------------
__global__ void scan_local_kernel() {
    __shared__ int smem[TILE];
    int b = blockIdx.x, tid = threadIdx.x;
    int i = b * TILE + tid;
    int v = (i < NN) ? g_deg[i] : 0;
    smem[tid] = v;
    __syncthreads();
    #pragma unroll
    for (int off = 1; off < TILE; off <<= 1) {
        int t = (tid >= off) ? smem[tid - off] : 0;
        __syncthreads();
        smem[tid] += t;
        __syncthreads();
    }
    if (i < NN) g_lscan[i] = smem[tid];
    if (tid == TILE - 1) g_bsum[b] = smem[tid];
}

// ----------------------------------------------------------------------------
// 3b) scan of 49 block sums (single tiny block)
// ----------------------------------------------------------------------------
__global__ void scan_bsum_kernel() {
    __shared__ int s[64];
    int tid = threadIdx.x;
    int v = (tid < NBLK) ? g_bsum[tid] : 0;
    s[tid] = v;
    __syncthreads();
    #pragma unroll
    for (int off = 1; off < 64; off <<= 1) {
        int t = (tid >= off) ? s[tid - off] : 0;
        __syncthreads();
        s[tid] += t;
        __syncthreads();
    }
    if (tid < NBLK) g_boff[tid] = s[tid] - v;   // exclusive
}

// ----------------------------------------------------------------------------
// 3c) finalize rowptr + cursor
// ----------------------------------------------------------------------------
__global__ void scan_finalize_kernel() {
    int i = blockIdx.x * blockDim.x + threadIdx.x;
    if (i >= NN) return;
    int incl = g_lscan[i] + g_boff[i / TILE];
    g_rowptr[i + 1] = incl;
    g_cursor[i] = incl - g_deg[i];
    if (i == 0) g_rowptr[0] = 0;
}

// ----------------------------------------------------------------------------
// 4) scatter edges into CSR-by-dst slots; single 8B packed store per edge
// ----------------------------------------------------------------------------
__global__ void fill_kernel(const int* __restrict__ src,
                            const int* __restrict__ dst,
                            const float* __restrict__ w) {
    int e = blockIdx.x * blockDim.x + threadIdx.x;
    if (e >= EE) return;
    int d = dst[e];
    int pos = atomicAdd(&g_cursor[d], 1);
    g_csr[pos] = make_int2(src[e], __float_as_int(w[e]));
}

// ----------------------------------------------------------------------------
// 5) SpMM hop: one warp per dst row. Lanes hold float2 (64 floats / 32 lanes).
//    hout[row] = sum_e w_e * h[src_e] ;  out[row] += 0.25 * hout[row]
//    LAST=true skips the hout store (value never consumed again).
// ----------------------------------------------------------------------------
template <bool LAST>
__global__ void spmm_kernel(const float* __restrict__ h,
                            float* __restrict__ hout,
                            float* __restrict__ out) {
    int warps_per_block = blockDim.x >> 5;
    int row = blockIdx.x * warps_per_block + (threadIdx.x >> 5);
    if (row >= NN) return;
    int lane = threadIdx.x & 31;

    int beg = g_rowptr[row];
    int end = g_rowptr[row + 1];

    const float2* __restrict__ h2 = (const float2*)h;

    float2 a0 = make_float2(0.f, 0.f);
    float2 a1 = make_float2(0.f, 0.f);
    float2 a2 = make_float2(0.f, 0.f);
    float2 a3 = make_float2(0.f, 0.f);

    int j = beg;
    // 4-way unroll: 4 independent gathers in flight per iteration
    for (; j + 3 < end; j += 4) {
        int2 e0 = __ldg(&g_csr[j]);
        int2 e1 = __ldg(&g_csr[j + 1]);
        int2 e2 = __ldg(&g_csr[j + 2]);
        int2 e3 = __ldg(&g_csr[j + 3]);
        float2 x0 = h2[e0.x * 32 + lane];
        float2 x1 = h2[e1.x * 32 + lane];
        float2 x2 = h2[e2.x * 32 + lane];
        float2 x3 = h2[e3.x * 32 + lane];
        float w0 = __int_as_float(e0.y), w1 = __int_as_float(e1.y);
        float w2 = __int_as_float(e2.y), w3 = __int_as_float(e3.y);
        a0.x += w0 * x0.x; a0.y += w0 * x0.y;
        a1.x += w1 * x1.x; a1.y += w1 * x1.y;
        a2.x += w2 * x2.x; a2.y += w2 * x2.y;
        a3.x += w3 * x3.x; a3.y += w3 * x3.y;
    }
    for (; j < end; j++) {
        int2 e0 = __ldg(&g_csr[j]);
        float2 x0 = h2[e0.x * 32 + lane];
        float w0 = __int_as_float(e0.y);
        a0.x += w0 * x0.x; a0.y += w0 * x0.y;
    }

    float2 acc = make_float2((a0.x + a1.x) + (a2.x + a3.x),
                             (a0.y + a1.y) + (a2.y + a3.y));

    int idx = row * 32 + lane;
    if (!LAST) ((float2*)hout)[idx] = acc;

    float2* o2 = (float2*)out + idx;
    float2 ov = *o2;
    ov.x += 0.25f * acc.x;
    ov.y += 0.25f * acc.y;
    *o2 = ov;
}

// ----------------------------------------------------------------------------
// launch
// ----------------------------------------------------------------------------
extern "C" void kernel_launch(void* const* d_in, const int* in_sizes, int n_in,
                              void* d_out, int out_size) {
    const float* x   = (const float*)d_in[0];
    const float* w   = (const float*)d_in[1];
    const int*   src = (const int*)d_in[2];
    const int*   dst = (const int*)d_in[3];
    float*       out = (float*)d_out;

    (void)in_sizes; (void)n_in; (void)out_size;

    float* hA; float* hB;
    cudaGetSymbolAddress((void**)&hA, g_h);
    cudaGetSymbolAddress((void**)&hB, g_t);

    // 1) init (also zeroes degree histogram)
    init_kernel<<<1024, 256>>>((const float4*)x, (float4*)out);
    // 2) histogram
    count_kernel<<<(EE + 255) / 256, 256>>>(dst);
    // 3) parallel scan (3 phases, each ~1 wave)
    scan_local_kernel<<<NBLK, TILE>>>();
    scan_bsum_kernel<<<1, 64>>>();
    scan_finalize_kernel<<<(NN + 255) / 256, 256>>>();
    // 4) CSR scatter (packed 8B per edge)
    fill_kernel<<<(EE + 255) / 256, 256>>>(src, dst, w);

    // 5) K=3 hops, ping-pong h buffers, fused residual (+0.25*h) into out
    const int WPB = 8;                    // 8 warps (rows) per block
    dim3 blk(WPB * 32);
    dim3 grd((NN + WPB - 1) / WPB);
    spmm_kernel<false><<<grd, blk>>>(hA, hB, out);   // hop 1: x    -> g_t
    spmm_kernel<false><<<grd, blk>>>(hB, hA, out);   // hop 2: g_t  -> g_h
    spmm_kernel<true ><<<grd, blk>>>(hA, hB, out);   // hop 3: residual only
}

// round 4
// speedup vs baseline: 1.5360x; 1.0003x over previous
#include <cuda_runtime.h>
#include <cstdint>

// Problem constants (match reference_code)
#define NN 50000
#define EE 800000
#define DD 64

#define TILE 1024
#define NBLK ((NN + TILE - 1) / TILE)   // 49

// ----------------------------------------------------------------------------
// Scratch (device globals; no allocation allowed)
// ----------------------------------------------------------------------------
__device__ float g_h[NN * DD];      // ping
__device__ float g_t[NN * DD];      // pong
__device__ int   g_deg[NN];         // in-degree histogram
__device__ int   g_rowptr[NN + 1];  // CSR row pointers (by dst)
__device__ int   g_cursor[NN];      // scatter cursors
__device__ int   g_lscan[NN];       // per-block inclusive scan
__device__ int   g_bsum[NBLK];      // block sums
__device__ int   g_boff[NBLK];      // exclusive block offsets
__device__ int2  g_csr[EE];         // packed {src, w_bits} per CSR slot

// ----------------------------------------------------------------------------
// 1) init: g_h = x ; out = 0.25*x ; zero degree histogram  (float4 vectorized)
// ----------------------------------------------------------------------------
__global__ void init_kernel(const float4* __restrict__ x4, float4* __restrict__ out4) {
    int i = blockIdx.x * blockDim.x + threadIdx.x;
    int stride = gridDim.x * blockDim.x;
    float4* h4 = (float4*)g_h;
    const int n4 = NN * DD / 4;
    for (int idx = i; idx < n4; idx += stride) {
        float4 v = x4[idx];
        h4[idx] = v;
        float4 o = make_float4(0.25f * v.x, 0.25f * v.y, 0.25f * v.z, 0.25f * v.w);
        out4[idx] = o;
    }
    for (int idx = i; idx < NN; idx += stride) g_deg[idx] = 0;
}

// ----------------------------------------------------------------------------
// 2) count in-degree per dst (no-return atomic -> REDG)
// ----------------------------------------------------------------------------
__global__ void count_kernel(const int* __restrict__ dst) {
    int e = blockIdx.x * blockDim.x + threadIdx.x;
    if (e < EE) atomicAdd(&g_deg[dst[e]], 1);
}

// ----------------------------------------------------------------------------
// 3a) per-block inclusive scan of g_deg (49 blocks, one wave)
// ----------------------------------------------------------------------------
__global__ void scan_local_kernel() {
    __shared__ int smem[TILE];
    int b = blockIdx.x, tid = threadIdx.x;
    int i = b * TILE + tid;
    int v = (i < NN) ? g_deg[i] : 0;
    smem[tid] = v;
    __syncthreads();
    #pragma unroll
    for (int off = 1; off < TILE; off <<= 1) {
        int t = (tid >= off) ? smem[tid - off] : 0;
        __syncthreads();
        smem[tid] += t;
        __syncthreads();
    }
    if (i < NN) g_lscan[i] = smem[tid];
    if (tid == TILE - 1) g_bsum[b] = smem[tid];
}

// ----------------------------------------------------------------------------
// 3b) scan of 49 block sums (single tiny block)
// ----------------------------------------------------------------------------
__global__ void scan_bsum_kernel() {
    __shared__ int s[64];
    int tid = threadIdx.x;
    int v = (tid < NBLK) ? g_bsum[tid] : 0;
    s[tid] = v;
    __syncthreads();
    #pragma unroll
    for (int off = 1; off < 64; off <<= 1) {
        int t = (tid >= off) ? s[tid - off] : 0;
        __syncthreads();
        s[tid] += t;
        __syncthreads();
    }
    if (tid < NBLK) g_boff[tid] = s[tid] - v;   // exclusive
}

// ----------------------------------------------------------------------------
// 3c) finalize rowptr + cursor
// ----------------------------------------------------------------------------
__global__ void scan_finalize_kernel() {
    int i = blockIdx.x * blockDim.x + threadIdx.x;
    if (i >= NN) return;
    int incl = g_lscan[i] + g_boff[i / TILE];
    g_rowptr[i + 1] = incl;
    g_cursor[i] = incl - g_deg[i];
    if (i == 0) g_rowptr[0] = 0;
}

// ----------------------------------------------------------------------------
// 4) scatter edges into CSR-by-dst slots; single 8B packed store per edge
// ----------------------------------------------------------------------------
__global__ void fill_kernel(const int* __restrict__ src,
                            const int* __restrict__ dst,
                            const float* __restrict__ w) {
    int e = blockIdx.x * blockDim.x + threadIdx.x;
    if (e >= EE) return;
    int d = dst[e];
    int pos = atomicAdd(&g_cursor[d], 1);
    g_csr[pos] = make_int2(src[e], __float_as_int(w[e]));
}

// ----------------------------------------------------------------------------
// 5) SpMM hop: one warp per dst row. Lanes hold float2 (64 floats / 32 lanes).
//    hout[row] = sum_e w_e * h[src_e] ;  out[row] += 0.25 * hout[row]
//    LAST=true skips the hout store (value never consumed again).
// ----------------------------------------------------------------------------
template <bool LAST>
__global__ void spmm_kernel(const float* __restrict__ h,
                            float* __restrict__ hout,
                            float* __restrict__ out) {
    int warps_per_block = blockDim.x >> 5;
    int row = blockIdx.x * warps_per_block + (threadIdx.x >> 5);
    if (row >= NN) return;
    int lane = threadIdx.x & 31;

    int beg = g_rowptr[row];
    int end = g_rowptr[row + 1];

    const float2* __restrict__ h2 = (const float2*)h;

    float2 a0 = make_float2(0.f, 0.f);
    float2 a1 = make_float2(0.f, 0.f);
    float2 a2 = make_float2(0.f, 0.f);
    float2 a3 = make_float2(0.f, 0.f);

    int j = beg;
    // 4-way unroll: 4 independent gathers in flight per iteration
    for (; j + 3 < end; j += 4) {
        int2 e0 = __ldg(&g_csr[j]);
        int2 e1 = __ldg(&g_csr[j + 1]);
        int2 e2 = __ldg(&g_csr[j + 2]);
        int2 e3 = __ldg(&g_csr[j + 3]);
        float2 x0 = h2[e0.x * 32 + lane];
        float2 x1 = h2[e1.x * 32 + lane];
        float2 x2 = h2[e2.x * 32 + lane];
        float2 x3 = h2[e3.x * 32 + lane];
        float w0 = __int_as_float(e0.y), w1 = __int_as_float(e1.y);
        float w2 = __int_as_float(e2.y), w3 = __int_as_float(e3.y);
        a0.x += w0 * x0.x; a0.y += w0 * x0.y;
        a1.x += w1 * x1.x; a1.y += w1 * x1.y;
        a2.x += w2 * x2.x; a2.y += w2 * x2.y;
        a3.x += w3 * x3.x; a3.y += w3 * x3.y;
    }
    for (; j < end; j++) {
        int2 e0 = __ldg(&g_csr[j]);
        float2 x0 = h2[e0.x * 32 + lane];
        float w0 = __int_as_float(e0.y);
        a0.x += w0 * x0.x; a0.y += w0 * x0.y;
    }

    float2 acc = make_float2((a0.x + a1.x) + (a2.x + a3.x),
                             (a0.y + a1.y) + (a2.y + a3.y));

    int idx = row * 32 + lane;
    if (!LAST) ((float2*)hout)[idx] = acc;

    float2* o2 = (float2*)out + idx;
    float2 ov = *o2;
    ov.x += 0.25f * acc.x;
    ov.y += 0.25f * acc.y;
    *o2 = ov;
}

// ----------------------------------------------------------------------------
// launch
// ----------------------------------------------------------------------------
extern "C" void kernel_launch(void* const* d_in, const int* in_sizes, int n_in,
                              void* d_out, int out_size) {
    const float* x   = (const float*)d_in[0];
    const float* w   = (const float*)d_in[1];
    const int*   src = (const int*)d_in[2];
    const int*   dst = (const int*)d_in[3];
    float*       out = (float*)d_out;

    (void)in_sizes; (void)n_in; (void)out_size;

    float* hA; float* hB;
    cudaGetSymbolAddress((void**)&hA, g_h);
    cudaGetSymbolAddress((void**)&hB, g_t);

    // 1) init (also zeroes degree histogram)
    init_kernel<<<1024, 256>>>((const float4*)x, (float4*)out);
    // 2) histogram
    count_kernel<<<(EE + 255) / 256, 256>>>(dst);
    // 3) parallel scan (3 phases, each ~1 wave)
    scan_local_kernel<<<NBLK, TILE>>>();
    scan_bsum_kernel<<<1, 64>>>();
    scan_finalize_kernel<<<(NN + 255) / 256, 256>>>();
    // 4) CSR scatter (packed 8B per edge)
    fill_kernel<<<(EE + 255) / 256, 256>>>(src, dst, w);

    // 5) K=3 hops, ping-pong h buffers, fused residual (+0.25*h) into out
    const int WPB = 8;                    // 8 warps (rows) per block
    dim3 blk(WPB * 32);
    dim3 grd((NN + WPB - 1) / WPB);
    spmm_kernel<false><<<grd, blk>>>(hA, hB, out);   // hop 1: x    -> g_t
    spmm_kernel<false><<<grd, blk>>>(hB, hA, out);   // hop 2: g_t  -> g_h
    spmm_kernel<true ><<<grd, blk>>>(hA, hB, out);   // hop 3: residual only
}

// round 5
// speedup vs baseline: 1.5403x; 1.0028x over previous
#include <cuda_runtime.h>
#include <cuda_fp16.h>
#include <cstdint>

// Problem constants (match reference_code)
#define NN 50000
#define EE 800000
#define DD 64

#define TILE 1024
#define NBLK ((NN + TILE - 1) / TILE)   // 49

// ----------------------------------------------------------------------------
// Scratch (device globals; no allocation allowed)
// ----------------------------------------------------------------------------
__device__ __half g_h[NN * DD];     // ping (fp16 inter-hop tensor)
__device__ __half g_t[NN * DD];     // pong
__device__ int    g_deg[NN];        // in-degree histogram
__device__ int    g_rowptr[NN + 1]; // CSR row pointers (by dst)
__device__ int    g_cursor[NN];     // scatter cursors
__device__ int    g_lscan[NN];      // per-block inclusive scan
__device__ int    g_bsum[NBLK];     // block sums
__device__ int2   g_csr[EE];        // packed {src, w_bits} per CSR slot

// ----------------------------------------------------------------------------
// 1) init: g_h = fp16(x) ; out = 0.25*x ; zero degree histogram
// ----------------------------------------------------------------------------
__global__ void init_kernel(const float4* __restrict__ x4, float4* __restrict__ out4) {
    int i = blockIdx.x * blockDim.x + threadIdx.x;
    int stride = gridDim.x * blockDim.x;
    __half2* h2 = (__half2*)g_h;
    const int n4 = NN * DD / 4;
    for (int idx = i; idx < n4; idx += stride) {
        float4 v = x4[idx];
        h2[idx * 2 + 0] = __floats2half2_rn(v.x, v.y);
        h2[idx * 2 + 1] = __floats2half2_rn(v.z, v.w);
        out4[idx] = make_float4(0.25f * v.x, 0.25f * v.y, 0.25f * v.z, 0.25f * v.w);
    }
    for (int idx = i; idx < NN; idx += stride) g_deg[idx] = 0;
}

// ----------------------------------------------------------------------------
// 2) count in-degree per dst; 4 edges per thread (EE % 4 == 0)
// ----------------------------------------------------------------------------
__global__ void count_kernel(const int4* __restrict__ dst4) {
    int t = blockIdx.x * blockDim.x + threadIdx.x;
    if (t >= EE / 4) return;
    int4 d = dst4[t];
    atomicAdd(&g_deg[d.x], 1);
    atomicAdd(&g_deg[d.y], 1);
    atomicAdd(&g_deg[d.z], 1);
    atomicAdd(&g_deg[d.w], 1);
}

// ----------------------------------------------------------------------------
// 3a) per-block inclusive scan of g_deg (shuffle-based, 2 barriers)
// ----------------------------------------------------------------------------
__global__ void scan_local_kernel() {
    __shared__ int wsum[32];
    int b = blockIdx.x, tid = threadIdx.x;
    int i = b * TILE + tid;
    int lane = tid & 31, wid = tid >> 5;
    int v = (i < NN) ? g_deg[i] : 0;
    int s = v;
    #pragma unroll
    for (int off = 1; off < 32; off <<= 1) {
        int t = __shfl_up_sync(0xFFFFFFFF, s, off);
        if (lane >= off) s += t;
    }
    if (lane == 31) wsum[wid] = s;
    __syncthreads();
    if (wid == 0) {
        int ws = wsum[lane];
        #pragma unroll
        for (int off = 1; off < 32; off <<= 1) {
            int t = __shfl_up_sync(0xFFFFFFFF, ws, off);
            if (lane >= off) ws += t;
        }
        wsum[lane] = ws;
    }
    __syncthreads();
    int incl = s + (wid > 0 ? wsum[wid - 1] : 0);
    if (i < NN) g_lscan[i] = incl;
    if (tid == TILE - 1) g_bsum[b] = incl;
}

// ----------------------------------------------------------------------------
// 3b) finalize rowptr + cursor; each 256-block lies inside one 1024-tile,
//     so one thread sums the <=49 bsum prefix for the whole block.
// ----------------------------------------------------------------------------
__global__ void scan_finalize_kernel() {
    __shared__ int boff_s;
    int tile = (blockIdx.x * 256) / TILE;
    if (threadIdx.x == 0) {
        int sum = 0;
        #pragma unroll 8
        for (int j = 0; j < tile; j++) sum += g_bsum[j];
        boff_s = sum;
    }
    __syncthreads();
    int i = blockIdx.x * 256 + threadIdx.x;
    if (i >= NN) return;
    int incl = g_lscan[i] + boff_s;
    g_rowptr[i + 1] = incl;
    g_cursor[i] = incl - g_deg[i];
    if (i == 0) g_rowptr[0] = 0;
}

// ----------------------------------------------------------------------------
// 4) scatter edges into CSR-by-dst; 4 edges per thread, vectorized reads,
//    single 8B packed store per edge.
// ----------------------------------------------------------------------------
__global__ void fill_kernel(const int4* __restrict__ src4,
                            const int4* __restrict__ dst4,
                            const float4* __restrict__ w4) {
    int t = blockIdx.x * blockDim.x + threadIdx.x;
    if (t >= EE / 4) return;
    int4   s = src4[t];
    int4   d = dst4[t];
    float4 w = w4[t];
    int p0 = atomicAdd(&g_cursor[d.x], 1);
    int p1 = atomicAdd(&g_cursor[d.y], 1);
    int p2 = atomicAdd(&g_cursor[d.z], 1);
    int p3 = atomicAdd(&g_cursor[d.w], 1);
    g_csr[p0] = make_int2(s.x, __float_as_int(w.x));
    g_csr[p1] = make_int2(s.y, __float_as_int(w.y));
    g_csr[p2] = make_int2(s.z, __float_as_int(w.z));
    g_csr[p3] = make_int2(s.w, __float_as_int(w.w));
}

// ----------------------------------------------------------------------------
// 5) SpMM hop: one warp per dst row. Lane holds half2 (2 features) -> the
//    per-edge gather is exactly one 128B L2 line per warp. Accumulate fp32.
//    hout[row] = fp16(sum_e w_e * h[src_e]) ;  out[row] += 0.25 * sum
// ----------------------------------------------------------------------------
template <bool LAST>
__global__ void spmm_kernel(const __half* __restrict__ h,
                            __half* __restrict__ hout,
                            float* __restrict__ out) {
    int warps_per_block = blockDim.x >> 5;
    int row = blockIdx.x * warps_per_block + (threadIdx.x >> 5);
    if (row >= NN) return;
    int lane = threadIdx.x & 31;

    int beg = g_rowptr[row];
    int end = g_rowptr[row + 1];

    const __half2* __restrict__ h2 = (const __half2*)h;

    float2 a0 = make_float2(0.f, 0.f);
    float2 a1 = make_float2(0.f, 0.f);
    float2 a2 = make_float2(0.f, 0.f);
    float2 a3 = make_float2(0.f, 0.f);

    int j = beg;
    for (; j + 3 < end; j += 4) {
        int2 e0 = __ldg(&g_csr[j]);
        int2 e1 = __ldg(&g_csr[j + 1]);
        int2 e2 = __ldg(&g_csr[j + 2]);
        int2 e3 = __ldg(&g_csr[j + 3]);
        float2 x0 = __half22float2(h2[e0.x * 32 + lane]);
        float2 x1 = __half22float2(h2[e1.x * 32 + lane]);
        float2 x2 = __half22float2(h2[e2.x * 32 + lane]);
        float2 x3 = __half22float2(h2[e3.x * 32 + lane]);
        float w0 = __int_as_float(e0.y), w1 = __int_as_float(e1.y);
        float w2 = __int_as_float(e2.y), w3 = __int_as_float(e3.y);
        a0.x += w0 * x0.x; a0.y += w0 * x0.y;
        a1.x += w1 * x1.x; a1.y += w1 * x1.y;
        a2.x += w2 * x2.x; a2.y += w2 * x2.y;
        a3.x += w3 * x3.x; a3.y += w3 * x3.y;
    }
    for (; j < end; j++) {
        int2 e0 = __ldg(&g_csr[j]);
        float2 x0 = __half22float2(h2[e0.x * 32 + lane]);
        float w0 = __int_as_float(e0.y);
        a0.x += w0 * x0.x; a0.y += w0 * x0.y;
    }

    float2 acc = make_float2((a0.x + a1.x) + (a2.x + a3.x),
                             (a0.y + a1.y) + (a2.y + a3.y));

    int idx = row * 32 + lane;
    if (!LAST) ((__half2*)hout)[idx] = __floats2half2_rn(acc.x, acc.y);

    float2* o2 = (float2*)out + idx;
    float2 ov = *o2;
    ov.x += 0.25f * acc.x;
    ov.y += 0.25f * acc.y;
    *o2 = ov;
}

// ----------------------------------------------------------------------------
// launch
// ----------------------------------------------------------------------------
extern "C" void kernel_launch(void* const* d_in, const int* in_sizes, int n_in,
                              void* d_out, int out_size) {
    const float* x   = (const float*)d_in[0];
    const float* w   = (const float*)d_in[1];
    const int*   src = (const int*)d_in[2];
    const int*   dst = (const int*)d_in[3];
    float*       out = (float*)d_out;

    (void)in_sizes; (void)n_in; (void)out_size;

    __half* hA; __half* hB;
    cudaGetSymbolAddress((void**)&hA, g_h);
    cudaGetSymbolAddress((void**)&hB, g_t);

    // 1) init (also zeroes degree histogram)
    init_kernel<<<1024, 256>>>((const float4*)x, (float4*)out);
    // 2) histogram (4 edges/thread)
    count_kernel<<<(EE / 4 + 255) / 256, 256>>>((const int4*)dst);
    // 3) parallel scan (2 phases)
    scan_local_kernel<<<NBLK, TILE>>>();
    scan_finalize_kernel<<<(NN + 255) / 256, 256>>>();
    // 4) CSR scatter (4 edges/thread, packed 8B per edge)
    fill_kernel<<<(EE / 4 + 255) / 256, 256>>>((const int4*)src, (const int4*)dst,
                                               (const float4*)w);

    // 5) K=3 hops, ping-pong fp16 h buffers, fused residual (+0.25*h) into out
    const int WPB = 8;
    dim3 blk(WPB * 32);
    dim3 grd((NN + WPB - 1) / WPB);
    spmm_kernel<false><<<grd, blk>>>(hA, hB, out);   // hop 1: x    -> g_t
    spmm_kernel<false><<<grd, blk>>>(hB, hA, out);   // hop 2: g_t  -> g_h
    spmm_kernel<true ><<<grd, blk>>>(hA, hB, out);   // hop 3: residual only
}

// round 6
// speedup vs baseline: 1.7831x; 1.1576x over previous
#include <cuda_runtime.h>
#include <cuda_fp16.h>
#include <cstdint>

// Problem constants (match reference_code)
#define NN 50000
#define EE 800000
#define DD 64

#define TILE 1024
#define NBLK ((NN + TILE - 1) / TILE)   // 49

// ----------------------------------------------------------------------------
// Scratch (device globals; no allocation allowed)
// ----------------------------------------------------------------------------
__device__ __half g_h[NN * DD];     // ping (fp16 inter-hop tensor)
__device__ __half g_t[NN * DD];     // pong
__device__ int    g_deg[NN];        // in-degree histogram
__device__ int    g_rowptr[NN + 1]; // CSR row pointers (by dst)
__device__ int    g_cursor[NN];     // scatter cursors
__device__ int    g_lscan[NN];      // per-block inclusive scan
__device__ int    g_bsum[NBLK];     // block sums
__device__ int2   g_csr[EE];        // packed {src, w_bits} per CSR slot

// ----------------------------------------------------------------------------
// 1) init: g_h = fp16(x) ; out = 0.25*x ; zero degree histogram
// ----------------------------------------------------------------------------
__global__ void init_kernel(const float4* __restrict__ x4, float4* __restrict__ out4) {
    int i = blockIdx.x * blockDim.x + threadIdx.x;
    int stride = gridDim.x * blockDim.x;
    __half2* h2 = (__half2*)g_h;
    const int n4 = NN * DD / 4;
    for (int idx = i; idx < n4; idx += stride) {
        float4 v = x4[idx];
        h2[idx * 2 + 0] = __floats2half2_rn(v.x, v.y);
        h2[idx * 2 + 1] = __floats2half2_rn(v.z, v.w);
        out4[idx] = make_float4(0.25f * v.x, 0.25f * v.y, 0.25f * v.z, 0.25f * v.w);
    }
    for (int idx = i; idx < NN; idx += stride) g_deg[idx] = 0;
}

// ----------------------------------------------------------------------------
// 2) count in-degree per dst; 4 edges per thread (EE % 4 == 0)
// ----------------------------------------------------------------------------
__global__ void count_kernel(const int4* __restrict__ dst4) {
    int t = blockIdx.x * blockDim.x + threadIdx.x;
    if (t >= EE / 4) return;
    int4 d = dst4[t];
    atomicAdd(&g_deg[d.x], 1);
    atomicAdd(&g_deg[d.y], 1);
    atomicAdd(&g_deg[d.z], 1);
    atomicAdd(&g_deg[d.w], 1);
}

// ----------------------------------------------------------------------------
// 3a) per-block inclusive scan of g_deg (shuffle-based, 2 barriers)
// ----------------------------------------------------------------------------
__global__ void scan_local_kernel() {
    __shared__ int wsum[32];
    int b = blockIdx.x, tid = threadIdx.x;
    int i = b * TILE + tid;
    int lane = tid & 31, wid = tid >> 5;
    int v = (i < NN) ? g_deg[i] : 0;
    int s = v;
    #pragma unroll
    for (int off = 1; off < 32; off <<= 1) {
        int t = __shfl_up_sync(0xFFFFFFFF, s, off);
        if (lane >= off) s += t;
    }
    if (lane == 31) wsum[wid] = s;
    __syncthreads();
    if (wid == 0) {
        int ws = wsum[lane];
        #pragma unroll
        for (int off = 1; off < 32; off <<= 1) {
            int t = __shfl_up_sync(0xFFFFFFFF, ws, off);
            if (lane >= off) ws += t;
        }
        wsum[lane] = ws;
    }
    __syncthreads();
    int incl = s + (wid > 0 ? wsum[wid - 1] : 0);
    if (i < NN) g_lscan[i] = incl;
    if (tid == TILE - 1) g_bsum[b] = incl;
}

// ----------------------------------------------------------------------------
// 3b) finalize rowptr + cursor. Block offset = sum of bsums for tiles before
//     this block's tile, computed warp-parallel (loads in parallel + shfl
//     reduce) instead of one thread's ~50 dependent L2 loads.
// ----------------------------------------------------------------------------
__global__ void scan_finalize_kernel() {
    __shared__ int boff_s;
    int tile = (blockIdx.x * 256) / TILE;   // this block's 1024-tile index
    if (threadIdx.x < 32) {
        int lane = threadIdx.x;
        int v = 0;
        if (lane < tile)      v  = g_bsum[lane];
        if (lane + 32 < tile) v += g_bsum[lane + 32];
        #pragma unroll
        for (int o = 16; o > 0; o >>= 1) v += __shfl_down_sync(0xFFFFFFFF, v, o);
        if (lane == 0) boff_s = v;
    }
    __syncthreads();
    int i = blockIdx.x * 256 + threadIdx.x;
    if (i >= NN) return;
    int incl = g_lscan[i] + boff_s;
    g_rowptr[i + 1] = incl;
    g_cursor[i] = incl - g_deg[i];
    if (i == 0) g_rowptr[0] = 0;
}

// ----------------------------------------------------------------------------
// 4) scatter edges into CSR-by-dst; 4 edges per thread, vectorized reads,
//    single 8B packed store per edge.
// ----------------------------------------------------------------------------
__global__ void fill_kernel(const int4* __restrict__ src4,
                            const int4* __restrict__ dst4,
                            const float4* __restrict__ w4) {
    int t = blockIdx.x * blockDim.x + threadIdx.x;
    if (t >= EE / 4) return;
    int4   s = src4[t];
    int4   d = dst4[t];
    float4 w = w4[t];
    int p0 = atomicAdd(&g_cursor[d.x], 1);
    int p1 = atomicAdd(&g_cursor[d.y], 1);
    int p2 = atomicAdd(&g_cursor[d.z], 1);
    int p3 = atomicAdd(&g_cursor[d.w], 1);
    g_csr[p0] = make_int2(s.x, __float_as_int(w.x));
    g_csr[p1] = make_int2(s.y, __float_as_int(w.y));
    g_csr[p2] = make_int2(s.z, __float_as_int(w.z));
    g_csr[p3] = make_int2(s.w, __float_as_int(w.w));
}

// ----------------------------------------------------------------------------
// 5) SpMM hop: QUARTER-warp per dst row. 8 lanes x uint4 (8 halves) = 128B
//    covers a full fp16 feature row, so one warp serves 4 rows:
//      per 4 edges: 1 edge-LDG + 1 gather-LDG.128  (0.5 LDG issues/edge,
//      ~3.5 warp-inst/edge vs ~8 before). Accumulate fp32.
//    hout[row] = fp16(sum_e w_e * h[src_e]) ;  out[row] += 0.25 * sum
// ----------------------------------------------------------------------------
template <bool LAST>
__global__ void spmm_kernel(const __half* __restrict__ h,
                            __half* __restrict__ hout,
                            float* __restrict__ out) {
    int wid  = threadIdx.x >> 5;
    int pair = blockIdx.x * (blockDim.x >> 5) + wid;   // warp index
    int lane = threadIdx.x & 31;
    int q     = lane >> 3;        // quarter 0..3
    int flane = lane & 7;         // lane within quarter
    int row = pair * 4 + q;
    if (row >= NN) return;

    int beg = g_rowptr[row];
    int end = g_rowptr[row + 1];

    const uint4* __restrict__ h8 = (const uint4*)h;   // 8 halves per uint4; row = 8 uint4

    // 8 fp32 accumulators per thread (features flane*8 .. flane*8+7), 2 chains
    float4 a0 = make_float4(0.f, 0.f, 0.f, 0.f);
    float4 b0 = make_float4(0.f, 0.f, 0.f, 0.f);
    float4 a1 = make_float4(0.f, 0.f, 0.f, 0.f);
    float4 b1 = make_float4(0.f, 0.f, 0.f, 0.f);

    int j = beg;
    for (; j + 1 < end; j += 2) {
        int2 e0 = __ldg(&g_csr[j]);
        int2 e1 = __ldg(&g_csr[j + 1]);
        uint4 p0 = __ldg(&h8[e0.x * 8 + flane]);
        uint4 p1 = __ldg(&h8[e1.x * 8 + flane]);
        float w0 = __int_as_float(e0.y);
        float w1 = __int_as_float(e1.y);
        {
            float2 f0 = __half22float2(*(__half2*)&p0.x);
            float2 f1 = __half22float2(*(__half2*)&p0.y);
            float2 f2 = __half22float2(*(__half2*)&p0.z);
            float2 f3 = __half22float2(*(__half2*)&p0.w);
            a0.x += w0 * f0.x; a0.y += w0 * f0.y; a0.z += w0 * f1.x; a0.w += w0 * f1.y;
            b0.x += w0 * f2.x; b0.y += w0 * f2.y; b0.z += w0 * f3.x; b0.w += w0 * f3.y;
        }
        {
            float2 f0 = __half22float2(*(__half2*)&p1.x);
            float2 f1 = __half22float2(*(__half2*)&p1.y);
            float2 f2 = __half22float2(*(__half2*)&p1.z);
            float2 f3 = __half22float2(*(__half2*)&p1.w);
            a1.x += w1 * f0.x; a1.y += w1 * f0.y; a1.z += w1 * f1.x; a1.w += w1 * f1.y;
            b1.x += w1 * f2.x; b1.y += w1 * f2.y; b1.z += w1 * f3.x; b1.w += w1 * f3.y;
        }
    }
    if (j < end) {
        int2 e0 = __ldg(&g_csr[j]);
        uint4 p0 = __ldg(&h8[e0.x * 8 + flane]);
        float w0 = __int_as_float(e0.y);
        float2 f0 = __half22float2(*(__half2*)&p0.x);
        float2 f1 = __half22float2(*(__half2*)&p0.y);
        float2 f2 = __half22float2(*(__half2*)&p0.z);
        float2 f3 = __half22float2(*(__half2*)&p0.w);
        a0.x += w0 * f0.x; a0.y += w0 * f0.y; a0.z += w0 * f1.x; a0.w += w0 * f1.y;
        b0.x += w0 * f2.x; b0.y += w0 * f2.y; b0.z += w0 * f3.x; b0.w += w0 * f3.y;
    }

    float4 A = make_float4(a0.x + a1.x, a0.y + a1.y, a0.z + a1.z, a0.w + a1.w);
    float4 B = make_float4(b0.x + b1.x, b0.y + b1.y, b0.z + b1.z, b0.w + b1.w);

    if (!LAST) {
        uint4 packed;
        *(__half2*)&packed.x = __floats2half2_rn(A.x, A.y);
        *(__half2*)&packed.y = __floats2half2_rn(A.z, A.w);
        *(__half2*)&packed.z = __floats2half2_rn(B.x, B.y);
        *(__half2*)&packed.w = __floats2half2_rn(B.z, B.w);
        ((uint4*)hout)[row * 8 + flane] = packed;
    }

    // out RMW: this thread owns floats [row*64 + flane*8, +8) -> two float4s
    float4* o = (float4*)out + row * 16 + flane * 2;
    float4 o0 = o[0], o1 = o[1];
    o0.x += 0.25f * A.x; o0.y += 0.25f * A.y; o0.z += 0.25f * A.z; o0.w += 0.25f * A.w;
    o1.x += 0.25f * B.x; o1.y += 0.25f * B.y; o1.z += 0.25f * B.z; o1.w += 0.25f * B.w;
    o[0] = o0; o[1] = o1;
}

// ----------------------------------------------------------------------------
// launch
// ----------------------------------------------------------------------------
extern "C" void kernel_launch(void* const* d_in, const int* in_sizes, int n_in,
                              void* d_out, int out_size) {
    const float* x   = (const float*)d_in[0];
    const float* w   = (const float*)d_in[1];
    const int*   src = (const int*)d_in[2];
    const int*   dst = (const int*)d_in[3];
    float*       out = (float*)d_out;

    (void)in_sizes; (void)n_in; (void)out_size;

    __half* hA; __half* hB;
    cudaGetSymbolAddress((void**)&hA, g_h);
    cudaGetSymbolAddress((void**)&hB, g_t);

    // 1) init (also zeroes degree histogram)
    init_kernel<<<1024, 256>>>((const float4*)x, (float4*)out);
    // 2) histogram (4 edges/thread)
    count_kernel<<<(EE / 4 + 255) / 256, 256>>>((const int4*)dst);
    // 3) parallel scan (2 phases)
    scan_local_kernel<<<NBLK, TILE>>>();
    scan_finalize_kernel<<<(NN + 255) / 256, 256>>>();
    // 4) CSR scatter (4 edges/thread, packed 8B per edge)
    fill_kernel<<<(EE / 4 + 255) / 256, 256>>>((const int4*)src, (const int4*)dst,
                                               (const float4*)w);

    // 5) K=3 hops, 4 rows per warp, ping-pong fp16 h buffers,
    //    fused residual (+0.25*h) into out
    const int WPB = 8;                            // 8 warps = 32 rows per block
    dim3 blk(WPB * 32);
    dim3 grd((NN + WPB * 4 - 1) / (WPB * 4));     // 1563 blocks
    spmm_kernel<false><<<grd, blk>>>(hA, hB, out);   // hop 1: x    -> g_t
    spmm_kernel<false><<<grd, blk>>>(hB, hA, out);   // hop 2: g_t  -> g_h
    spmm_kernel<true ><<<grd, blk>>>(hA, hB, out);   // hop 3: residual only
}

// round 7
// speedup vs baseline: 2.0960x; 1.1755x over previous
#include <cuda_runtime.h>
#include <cuda_fp16.h>
#include <cstdint>

// Problem constants (match reference_code)
#define NN 50000
#define EE 800000
#define DD 64

#define TILE 1024
#define NBLK ((NN + TILE - 1) / TILE)   // 49

// ----------------------------------------------------------------------------
// Scratch (device globals; no allocation allowed). BSS-zeroed at load, and
// fill_kernel re-zeroes g_deg / g_flag each call, so every graph replay sees
// the same initial state.
// ----------------------------------------------------------------------------
__device__ __half g_h[NN * DD];       // ping (fp16 inter-hop tensor)
__device__ __half g_t[NN * DD];       // pong
__device__ int    g_deg[NN];          // in-degree histogram (zero at entry)
__device__ int    g_rowptr[NN + 1];   // CSR row pointers (by dst)
__device__ int    g_cursor[NN];       // scatter cursors
__device__ volatile int g_bsum[NBLK]; // scan block sums
__device__ volatile int g_flag[NBLK]; // scan lookback flags (zero at entry)
__device__ int2   g_csr[EE];          // packed {src, w_bits} per CSR slot

// ----------------------------------------------------------------------------
// 1) init + count fused: g_h = fp16(x); out = 0.25*x; histogram of dst.
//    (g_deg enters zeroed: BSS on first call, fill_kernel afterwards.)
// ----------------------------------------------------------------------------
__global__ void init_count_kernel(const float4* __restrict__ x4,
                                  float4* __restrict__ out4,
                                  const int4* __restrict__ dst4) {
    int t = blockIdx.x * blockDim.x + threadIdx.x;
    int stride = gridDim.x * blockDim.x;
    __half2* h2 = (__half2*)g_h;
    const int n4 = NN * DD / 4;
    for (int idx = t; idx < n4; idx += stride) {
        float4 v = x4[idx];
        h2[idx * 2 + 0] = __floats2half2_rn(v.x, v.y);
        h2[idx * 2 + 1] = __floats2half2_rn(v.z, v.w);
        out4[idx] = make_float4(0.25f * v.x, 0.25f * v.y, 0.25f * v.z, 0.25f * v.w);
    }
    for (int e = t; e < EE / 4; e += stride) {
        int4 d = dst4[e];
        atomicAdd(&g_deg[d.x], 1);
        atomicAdd(&g_deg[d.y], 1);
        atomicAdd(&g_deg[d.z], 1);
        atomicAdd(&g_deg[d.w], 1);
    }
}

// ----------------------------------------------------------------------------
// 2) single-pass scan with decoupled lookback (49 blocks, all resident).
//    Produces g_rowptr and g_cursor in one launch.
// ----------------------------------------------------------------------------
__global__ void scan_kernel() {
    __shared__ int wsum[32];
    __shared__ int s_off;
    int b = blockIdx.x, tid = threadIdx.x;
    int i = b * TILE + tid;
    int lane = tid & 31, wid = tid >> 5;

    int v = (i < NN) ? g_deg[i] : 0;
    int s = v;
    #pragma unroll
    for (int off = 1; off < 32; off <<= 1) {
        int t = __shfl_up_sync(0xFFFFFFFF, s, off);
        if (lane >= off) s += t;
    }
    if (lane == 31) wsum[wid] = s;
    __syncthreads();
    if (wid == 0) {
        int ws = wsum[lane];
        #pragma unroll
        for (int off = 1; off < 32; off <<= 1) {
            int t = __shfl_up_sync(0xFFFFFFFF, ws, off);
            if (lane >= off) ws += t;
        }
        wsum[lane] = ws;
    }
    __syncthreads();
    int incl = s + (wid > 0 ? wsum[wid - 1] : 0);

    // publish block total, then lookback over predecessors (warp 0)
    if (tid == 0) {
        g_bsum[b] = wsum[31];
        __threadfence();
        g_flag[b] = 1;
    }
    if (wid == 0) {
        int acc = 0;
        for (int j = lane; j < b; j += 32) {
            while (g_flag[j] == 0) { }   // volatile spin; all 49 blocks resident
            acc += g_bsum[j];
        }
        #pragma unroll
        for (int o = 16; o > 0; o >>= 1) acc += __shfl_down_sync(0xFFFFFFFF, acc, o);
        if (lane == 0) s_off = acc;
    }
    __syncthreads();
    int offset = s_off;

    if (i < NN) {
        int e = incl + offset;
        g_rowptr[i + 1] = e;
        g_cursor[i] = e - v;
    }
    if (b == 0 && tid == 0) g_rowptr[0] = 0;
}

// ----------------------------------------------------------------------------
// 3) scatter edges into CSR-by-dst (4 edges/thread, packed 8B stores).
//    Also re-zeroes g_deg and g_flag (their last readers have finished) so
//    the next replay sees pristine state.
// ----------------------------------------------------------------------------
__global__ void fill_kernel(const int4* __restrict__ src4,
                            const int4* __restrict__ dst4,
                            const float4* __restrict__ w4) {
    int t = blockIdx.x * blockDim.x + threadIdx.x;
    if (t < NN) g_deg[t] = 0;
    if (t < NBLK) g_flag[t] = 0;
    if (t >= EE / 4) return;
    int4   s = src4[t];
    int4   d = dst4[t];
    float4 w = w4[t];
    int p0 = atomicAdd(&g_cursor[d.x], 1);
    int p1 = atomicAdd(&g_cursor[d.y], 1);
    int p2 = atomicAdd(&g_cursor[d.z], 1);
    int p3 = atomicAdd(&g_cursor[d.w], 1);
    g_csr[p0] = make_int2(s.x, __float_as_int(w.x));
    g_csr[p1] = make_int2(s.y, __float_as_int(w.y));
    g_csr[p2] = make_int2(s.z, __float_as_int(w.z));
    g_csr[p3] = make_int2(s.w, __float_as_int(w.w));
}

// ----------------------------------------------------------------------------
// 4) SpMM hop: quarter-warp per dst row (8 lanes x uint4 = one 128B fp16 row).
//    8 shared fp32 accumulators (FMA reuse distance 8 > lat 4) + 4-deep load
//    pipeline for MLP; __launch_bounds__ caps regs for 4 blocks/SM occupancy.
// ----------------------------------------------------------------------------
__device__ __forceinline__ void acc8(float* a, float w, const uint4& p) {
    float2 f0 = __half22float2(*(const __half2*)&p.x);
    float2 f1 = __half22float2(*(const __half2*)&p.y);
    float2 f2 = __half22float2(*(const __half2*)&p.z);
    float2 f3 = __half22float2(*(const __half2*)&p.w);
    a[0] += w * f0.x; a[1] += w * f0.y;
    a[2] += w * f1.x; a[3] += w * f1.y;
    a[4] += w * f2.x; a[5] += w * f2.y;
    a[6] += w * f3.x; a[7] += w * f3.y;
}

template <bool LAST>
__global__ void __launch_bounds__(256, 4)
spmm_kernel(const __half* __restrict__ h,
            __half* __restrict__ hout,
            float* __restrict__ out) {
    int wid  = threadIdx.x >> 5;
    int warp = blockIdx.x * (blockDim.x >> 5) + wid;
    int lane = threadIdx.x & 31;
    int q     = lane >> 3;
    int flane = lane & 7;
    int row = warp * 4 + q;
    if (row >= NN) return;

    int beg = g_rowptr[row];
    int end = g_rowptr[row + 1];

    const uint4* __restrict__ h8 = (const uint4*)h;   // 8 halves per uint4

    float a[8] = {0.f, 0.f, 0.f, 0.f, 0.f, 0.f, 0.f, 0.f};

    int j = beg;
    for (; j + 3 < end; j += 4) {
        int2 e0 = __ldg(&g_csr[j]);
        int2 e1 = __ldg(&g_csr[j + 1]);
        int2 e2 = __ldg(&g_csr[j + 2]);
        int2 e3 = __ldg(&g_csr[j + 3]);
        uint4 p0 = __ldg(&h8[e0.x * 8 + flane]);
        uint4 p1 = __ldg(&h8[e1.x * 8 + flane]);
        uint4 p2 = __ldg(&h8[e2.x * 8 + flane]);
        uint4 p3 = __ldg(&h8[e3.x * 8 + flane]);
        acc8(a, __int_as_float(e0.y), p0);
        acc8(a, __int_as_float(e1.y), p1);
        acc8(a, __int_as_float(e2.y), p2);
        acc8(a, __int_as_float(e3.y), p3);
    }
    for (; j < end; j++) {
        int2 e0 = __ldg(&g_csr[j]);
        uint4 p0 = __ldg(&h8[e0.x * 8 + flane]);
        acc8(a, __int_as_float(e0.y), p0);
    }

    if (!LAST) {
        uint4 packed;
        *(__half2*)&packed.x = __floats2half2_rn(a[0], a[1]);
        *(__half2*)&packed.y = __floats2half2_rn(a[2], a[3]);
        *(__half2*)&packed.z = __floats2half2_rn(a[4], a[5]);
        *(__half2*)&packed.w = __floats2half2_rn(a[6], a[7]);
        ((uint4*)hout)[row * 8 + flane] = packed;
    }

    float4* o = (float4*)out + row * 16 + flane * 2;
    float4 o0 = o[0], o1 = o[1];
    o0.x += 0.25f * a[0]; o0.y += 0.25f * a[1];
    o0.z += 0.25f * a[2]; o0.w += 0.25f * a[3];
    o1.x += 0.25f * a[4]; o1.y += 0.25f * a[5];
    o1.z += 0.25f * a[6]; o1.w += 0.25f * a[7];
    o[0] = o0; o[1] = o1;
}

// ----------------------------------------------------------------------------
// launch (6 kernels total)
// ----------------------------------------------------------------------------
extern "C" void kernel_launch(void* const* d_in, const int* in_sizes, int n_in,
                              void* d_out, int out_size) {
    const float* x   = (const float*)d_in[0];
    const float* w   = (const float*)d_in[1];
    const int*   src = (const int*)d_in[2];
    const int*   dst = (const int*)d_in[3];
    float*       out = (float*)d_out;

    (void)in_sizes; (void)n_in; (void)out_size;

    __half* hA; __half* hB;
    cudaGetSymbolAddress((void**)&hA, g_h);
    cudaGetSymbolAddress((void**)&hB, g_t);

    // 1) init + histogram
    init_count_kernel<<<1024, 256>>>((const float4*)x, (float4*)out, (const int4*)dst);
    // 2) one-pass scan -> rowptr + cursor
    scan_kernel<<<NBLK, TILE>>>();
    // 3) CSR scatter (also resets g_deg / g_flag for the next replay)
    fill_kernel<<<(EE / 4 + 255) / 256, 256>>>((const int4*)src, (const int4*)dst,
                                               (const float4*)w);

    // 4-6) K=3 hops, 4 rows per warp, ping-pong fp16 h buffers,
    //      fused residual (+0.25*h) into out
    const int WPB = 8;                            // 8 warps = 32 rows per block
    dim3 blk(WPB * 32);
    dim3 grd((NN + WPB * 4 - 1) / (WPB * 4));     // 1563 blocks
    spmm_kernel<false><<<grd, blk>>>(hA, hB, out);   // hop 1: x    -> g_t
    spmm_kernel<false><<<grd, blk>>>(hB, hA, out);   // hop 2: g_t  -> g_h
    spmm_kernel<true ><<<grd, blk>>>(hA, hB, out);   // hop 3: residual only
}